// round 7
// baseline (speedup 1.0000x reference)
#include <cuda_runtime.h>
#include <cuda_bf16.h>

#define NKER 25
#define HP   8        // padded inner dim (6 feats + basis-sum + pad)
#define HROW 200      // NKER * HP floats per node
#define HW   150      // logical 25*6
#define JD   156      // 150 + 6 (H rows + x rows)
#define CD   78       // 75 Z cols + 3 root cols
#define MP   80       // sM pitch (floats), cols 78,79 zero
#define JPART 78      // j-rows per part
#define NMAX 50000
#define EMAX 1600000

// scratch (no cudaMalloc allowed)
__device__ float  g_H[NMAX * HROW];     // 40 MB, [n][k][8]: 6 feats, slot6=Σbasis(deg), slot7 pad
__device__ float  g_inv[NMAX];
__device__ float4 g_X8[NMAX * 2];       // x packed 32B-aligned: {x0..x5,0,0}
__device__ float4 g_Z4[NMAX * NKER];    // 20 MB, (z0,z1,z2,pad) per (n,kk)
__device__ float4 g_A4[NMAX];           // edge-2 accumulator
__device__ float  g_M[JD * CD];         // fused weight matrix

// ---------------------------------------------------------------------------
__global__ void k_zero(const float* __restrict__ x, float* __restrict__ dout, int N) {
    int i = blockIdx.x * blockDim.x + threadIdx.x;
    int stride = gridDim.x * blockDim.x;
    float4 z4 = make_float4(0.f, 0.f, 0.f, 0.f);
    float4* H4 = reinterpret_cast<float4*>(g_H);
    int nH4 = N * (HROW / 4);
    for (int t = i; t < nH4; t += stride) H4[t] = z4;
    int nZ = N * NKER;
    for (int t = i; t < nZ; t += stride) g_Z4[t] = z4;
    int nO = N * 3;
    for (int t = i; t < nO; t += stride) dout[t] = 0.f;
    for (int t = i; t < N; t += stride) {
        g_A4[t] = z4;
        const float2* x2 = reinterpret_cast<const float2*>(x) + t * 3;
        float2 xa = x2[0], xb = x2[1], xc = x2[2];
        g_X8[2 * t]     = make_float4(xa.x, xa.y, xb.x, xb.y);
        g_X8[2 * t + 1] = make_float4(xc.x, xc.y, 0.f, 0.f);
    }
}

// degree-1 open B-spline, K=5: 4 corners
__device__ __forceinline__ void spline4(float p0, float p1, float* b, int* id) {
    float v0 = p0 * 4.0f, v1 = p1 * 4.0f;
    float fl0 = floorf(v0), fl1 = floorf(v1);
    int i0 = (int)fl0, i1 = (int)fl1;
    i0 = min(max(i0, 0), 3);
    i1 = min(max(i1, 0), 3);
    float f0 = v0 - fl0, f1 = v1 - fl1;
    float g0 = 1.0f - f0, g1 = 1.0f - f1;
    b[0] = g0 * g1; b[1] = f0 * g1; b[2] = g0 * f1; b[3] = f0 * f1;
    int base = i0 + 5 * i1;
    id[0] = base; id[1] = base + 1; id[2] = base + 5; id[3] = base + 6;
}

// ---------------------------------------------------------------------------
// Edge pass 1: H[dst, idx_s, 0:6] += basis_s * x[src, :]; slot6 += basis_s
__global__ void k_edge1(const int* __restrict__ ei, const float* __restrict__ ps,
                        int E) {
    int e = blockIdx.x * blockDim.x + threadIdx.x;
    if (e >= E) return;
    int dst = ei[e];
    int src = ei[E + e];
    float2 p = reinterpret_cast<const float2*>(ps)[e];
    float b[4]; int id[4];
    spline4(p.x, p.y, b, id);
    float4 xa = __ldg(g_X8 + 2 * src);
    float4 xb = __ldg(g_X8 + 2 * src + 1);
    float4* Hd = reinterpret_cast<float4*>(g_H + (size_t)dst * HROW);
#pragma unroll
    for (int s = 0; s < 4; s++) {
        float bs = b[s];
        float4* hp = Hd + id[s] * 2;
        atomicAdd(hp,     make_float4(bs * xa.x, bs * xa.y, bs * xa.z, bs * xa.w));
        atomicAdd(hp + 1, make_float4(bs * xb.x, bs * xb.y, bs, 0.f));
    }
}

// ---------------------------------------------------------------------------
// Build fused M (156 x 78). Block j; 4 i-slices per col, smem reduce.
__global__ void k_buildM(const float* __restrict__ w, const float* __restrict__ rw,
                         const float* __restrict__ w1, const float* __restrict__ rw1) {
    __shared__ float sA[1024];
    __shared__ float red[CD][4];
    int j = blockIdx.x;
    int tid = threadIdx.x;
    const float* Arow = (j < HW) ? (w + (j / 6) * 6144 + (j % 6) * 1024)
                                 : (rw + (j - HW) * 1024);
    for (int i = tid; i < 1024; i += blockDim.x) sA[i] = Arow[i];
    __syncthreads();
    int c = tid >> 2, sl = tid & 3;
    if (c < CD) {
        const float* Bp = (c < 75) ? (w1 + (c / 3) * 3072 + (c % 3)) : (rw1 + (c - 75));
        float acc = 0.f;
        int i0 = sl * 256;
#pragma unroll 8
        for (int i = i0; i < i0 + 256; i++) acc = fmaf(sA[i], __ldg(Bp + i * 3), acc);
        red[c][sl] = acc;
    }
    __syncthreads();
    if (tid < CD)
        g_M[j * CD + tid] = (red[tid][0] + red[tid][1]) + (red[tid][2] + red[tid][3]);
}

// ---------------------------------------------------------------------------
// Z GEMM, j-split: blockIdx.y = part. part0 sums kernels 0..12, part1 sums
// kernels 13..24 plus the x rows. Each part scales by the full inverse degree
// (linear) and atomically accumulates into g_Z4 / dout.
__global__ void __launch_bounds__(128, 4)
k_zgemm_part(float* __restrict__ dout, int N) {
    __shared__ float sM[JPART * MP];   // 78*80*4 = 24960 B
    int tid = threadIdx.x;
    int part = blockIdx.y;
    int jg0 = part * JPART;            // global row offset into g_M

    for (int idx = tid; idx < JPART * MP; idx += 128) {
        int j = idx / MP, c = idx - j * MP;
        sM[idx] = (c < CD) ? g_M[(jg0 + j) * CD + c] : 0.f;
    }
    __syncthreads();

    int n = blockIdx.x * 128 + tid;
    if (n >= N) return;

    float acc[80];
#pragma unroll
    for (int c = 0; c < 80; c++) acc[c] = 0.f;

    const float4* H4 = reinterpret_cast<const float4*>(g_H + (size_t)n * HROW);
    const float*  Hf = g_H + (size_t)n * HROW;
    float d = 0.f;

    int k0 = (part == 0) ? 0 : 13;
    int k1 = (part == 0) ? 13 : NKER;

    for (int k = k0; k < k1; k++) {
        float4 h0 = __ldg(H4 + 2 * k);
        float4 h1 = __ldg(H4 + 2 * k + 1);
        d += h1.z;
        float av[6] = {h0.x, h0.y, h0.z, h0.w, h1.x, h1.y};
        int jb = (k - k0) * 6;
#pragma unroll
        for (int i = 0; i < 6; i++) {
            float a = av[i];
            const float4* m4 = reinterpret_cast<const float4*>(sM + (jb + i) * MP);
#pragma unroll
            for (int g = 0; g < 20; g++) {
                float4 b = m4[g];
                acc[4 * g + 0] = fmaf(a, b.x, acc[4 * g + 0]);
                acc[4 * g + 1] = fmaf(a, b.y, acc[4 * g + 1]);
                acc[4 * g + 2] = fmaf(a, b.z, acc[4 * g + 2]);
                acc[4 * g + 3] = fmaf(a, b.w, acc[4 * g + 3]);
            }
        }
    }

    // foreign slot6 values to get the full degree
    int f0 = (part == 0) ? 13 : 0;
    int f1 = (part == 0) ? NKER : 13;
    for (int k = f0; k < f1; k++) d += __ldg(Hf + k * HP + 6);

    float inv = 1.0f / fmaxf(d, 1.0f);
    if (part == 0) g_inv[n] = inv;
#pragma unroll
    for (int c = 0; c < 80; c++) acc[c] *= inv;

    if (part == 1) {
        // x part (rows 150..155 of M = local rows 72..77), unscaled
        float4 xa = __ldg(g_X8 + 2 * n);
        float4 xb = __ldg(g_X8 + 2 * n + 1);
        float xv[6] = {xa.x, xa.y, xa.z, xa.w, xb.x, xb.y};
#pragma unroll
        for (int i = 0; i < 6; i++) {
            float a = xv[i];
            const float4* m4 = reinterpret_cast<const float4*>(sM + (72 + i) * MP);
#pragma unroll
            for (int g = 0; g < 20; g++) {
                float4 b = m4[g];
                acc[4 * g + 0] = fmaf(a, b.x, acc[4 * g + 0]);
                acc[4 * g + 1] = fmaf(a, b.y, acc[4 * g + 1]);
                acc[4 * g + 2] = fmaf(a, b.z, acc[4 * g + 2]);
                acc[4 * g + 3] = fmaf(a, b.w, acc[4 * g + 3]);
            }
        }
    }

    float4* Zn = g_Z4 + (size_t)n * NKER;
#pragma unroll
    for (int kk = 0; kk < NKER; kk++)
        atomicAdd(Zn + kk, make_float4(acc[3 * kk], acc[3 * kk + 1], acc[3 * kk + 2], 0.f));
    atomicAdd(dout + n * 3 + 0, acc[75]);
    atomicAdd(dout + n * 3 + 1, acc[76]);
    atomicAdd(dout + n * 3 + 2, acc[77]);
}

// ---------------------------------------------------------------------------
// Edge pass 2: A4[dst] += sum_s basis1_s * Z[src, idx_s, :]  (one float4 atomic)
__global__ void k_edge2(const int* __restrict__ ei, const float* __restrict__ ps,
                        int E) {
    int e = blockIdx.x * blockDim.x + threadIdx.x;
    if (e >= E) return;
    int dst = ei[e];
    int src = ei[E + e];
    float2 p = reinterpret_cast<const float2*>(ps)[e];
    float b[4]; int id[4];
    spline4(p.x, p.y, b, id);
    const float4* Z = g_Z4 + (size_t)src * NKER;
    float a0 = 0.f, a1 = 0.f, a2 = 0.f;
#pragma unroll
    for (int s = 0; s < 4; s++) {
        float4 z = __ldg(Z + id[s]);
        a0 = fmaf(b[s], z.x, a0);
        a1 = fmaf(b[s], z.y, a1);
        a2 = fmaf(b[s], z.z, a2);
    }
    atomicAdd(g_A4 + dst, make_float4(a0, a1, a2, 0.f));
}

// ---------------------------------------------------------------------------
// Final: out[n] = root_term (already in dout) + inv[n] * A4[n]
__global__ void k_final(float* __restrict__ dout, int N) {
    int n = blockIdx.x * blockDim.x + threadIdx.x;
    if (n >= N) return;
    float4 a = g_A4[n];
    float inv = g_inv[n];
    dout[n * 3 + 0] += a.x * inv;
    dout[n * 3 + 1] += a.y * inv;
    dout[n * 3 + 2] += a.z * inv;
}

// ---------------------------------------------------------------------------
extern "C" void kernel_launch(void* const* d_in, const int* in_sizes, int n_in,
                              void* d_out, int out_size) {
    const float* x   = (const float*)d_in[0];
    const int*   ei  = (const int*)d_in[1];
    const float* ps  = (const float*)d_in[2];
    const float* ps1 = (const float*)d_in[3];
    const float* w   = (const float*)d_in[4];
    const float* rw  = (const float*)d_in[5];
    const float* w1  = (const float*)d_in[6];
    const float* rw1 = (const float*)d_in[7];
    float* dout = (float*)d_out;

    int N = in_sizes[0] / 6;
    int E = in_sizes[2] / 2;
    if (N > NMAX) N = NMAX;
    if (E > EMAX) E = EMAX;

    k_zero<<<2048, 256>>>(x, dout, N);
    k_edge1<<<(E + 255) / 256, 256>>>(ei, ps, E);
    k_buildM<<<JD, 320>>>(w, rw, w1, rw1);

    dim3 gz((N + 127) / 128, 2);
    k_zgemm_part<<<gz, 128>>>(dout, N);

    k_edge2<<<(E + 255) / 256, 256>>>(ei, ps1, E);
    k_final<<<(N + 255) / 256, 256>>>(dout, N);
}

// round 9
// speedup vs baseline: 1.0673x; 1.0673x over previous
#include <cuda_runtime.h>
#include <cuda_bf16.h>

#define NKER 25
#define HP   8        // padded inner dim (6 feats + basis-sum + pad)
#define HROW 200      // NKER * HP floats per node
#define HW   150      // logical 25*6
#define JD   156      // 150 + 6 (H rows + x rows)
#define CD   78       // 75 Z cols + 3 root cols
#define NG   26       // float4 col-groups (3 real cols each)
#define NGP  27       // padded row stride in float4 (bank stagger)
#define GH   13       // groups per half
#define NMAX 50000
#define EMAX 1600000

// scratch (no cudaMalloc allowed)
__device__ float  g_H[NMAX * HROW];     // 40 MB, [n][k][8]: 6 feats, slot6=Σbasis(deg), slot7 pad
__device__ float  g_inv[NMAX];
__device__ float4 g_X8[NMAX * 2];       // x packed 32B-aligned: {x0..x5,0,0}
__device__ float4 g_Z4[NMAX * NKER];    // 20 MB, (z0,z1,z2,pad) per (n,kk)
__device__ float4 g_A4[NMAX];           // edge-2 accumulator
__device__ float  g_M[JD * CD];         // fused weight matrix

// ---------------------------------------------------------------------------
__global__ void k_zero(const float* __restrict__ x, int N) {
    int i = blockIdx.x * blockDim.x + threadIdx.x;
    int stride = gridDim.x * blockDim.x;
    float4 z4 = make_float4(0.f, 0.f, 0.f, 0.f);
    float4* H4 = reinterpret_cast<float4*>(g_H);
    int nH4 = N * (HROW / 4);
    for (int t = i; t < nH4; t += stride) H4[t] = z4;
    for (int t = i; t < N; t += stride) {
        g_A4[t] = z4;
        const float2* x2 = reinterpret_cast<const float2*>(x) + t * 3;
        float2 xa = x2[0], xb = x2[1], xc = x2[2];
        g_X8[2 * t]     = make_float4(xa.x, xa.y, xb.x, xb.y);
        g_X8[2 * t + 1] = make_float4(xc.x, xc.y, 0.f, 0.f);
    }
}

// degree-1 open B-spline, K=5: 4 corners
__device__ __forceinline__ void spline4(float p0, float p1, float* b, int* id) {
    float v0 = p0 * 4.0f, v1 = p1 * 4.0f;
    float fl0 = floorf(v0), fl1 = floorf(v1);
    int i0 = (int)fl0, i1 = (int)fl1;
    i0 = min(max(i0, 0), 3);
    i1 = min(max(i1, 0), 3);
    float f0 = v0 - fl0, f1 = v1 - fl1;
    float g0 = 1.0f - f0, g1 = 1.0f - f1;
    b[0] = g0 * g1; b[1] = f0 * g1; b[2] = g0 * f1; b[3] = f0 * f1;
    int base = i0 + 5 * i1;
    id[0] = base; id[1] = base + 1; id[2] = base + 5; id[3] = base + 6;
}

// ---------------------------------------------------------------------------
// Edge pass 1: H[dst, idx_s, 0:6] += basis_s * x[src, :]; slot6 += basis_s
__global__ void k_edge1(const int* __restrict__ ei, const float* __restrict__ ps,
                        int E) {
    int e = blockIdx.x * blockDim.x + threadIdx.x;
    if (e >= E) return;
    int dst = ei[e];
    int src = ei[E + e];
    float2 p = reinterpret_cast<const float2*>(ps)[e];
    float b[4]; int id[4];
    spline4(p.x, p.y, b, id);
    float4 xa = __ldg(g_X8 + 2 * src);
    float4 xb = __ldg(g_X8 + 2 * src + 1);
    float4* Hd = reinterpret_cast<float4*>(g_H + (size_t)dst * HROW);
#pragma unroll
    for (int s = 0; s < 4; s++) {
        float bs = b[s];
        float4* hp = Hd + id[s] * 2;
        atomicAdd(hp,     make_float4(bs * xa.x, bs * xa.y, bs * xa.z, bs * xa.w));
        atomicAdd(hp + 1, make_float4(bs * xb.x, bs * xb.y, bs, 0.f));
    }
}

// ---------------------------------------------------------------------------
// Build fused M (156 x 78). Block j; 4 i-slices per col, smem reduce.
__global__ void k_buildM(const float* __restrict__ w, const float* __restrict__ rw,
                         const float* __restrict__ w1, const float* __restrict__ rw1) {
    __shared__ float sA[1024];
    __shared__ float red[CD][4];
    int j = blockIdx.x;
    int tid = threadIdx.x;
    const float* Arow = (j < HW) ? (w + (j / 6) * 6144 + (j % 6) * 1024)
                                 : (rw + (j - HW) * 1024);
    for (int i = tid; i < 1024; i += blockDim.x) sA[i] = Arow[i];
    __syncthreads();
    int c = tid >> 2, sl = tid & 3;
    if (c < CD) {
        const float* Bp = (c < 75) ? (w1 + (c / 3) * 3072 + (c % 3)) : (rw1 + (c - 75));
        float acc = 0.f;
        int i0 = sl * 256;
#pragma unroll 8
        for (int i = i0; i < i0 + 256; i++) acc = fmaf(sA[i], __ldg(Bp + i * 3), acc);
        red[c][sl] = acc;
    }
    __syncthreads();
    if (tid < CD)
        g_M[j * CD + tid] = (red[tid][0] + red[tid][1]) + (red[tid][2] + red[tid][3]);
}

// ---------------------------------------------------------------------------
// Z GEMM: 2 nodes per thread x 39-col half. Per j: 13 LDS.128 -> 78 FMA.
// Block = 128 threads = 64 node-pairs duplicated over 2 column halves.
__global__ void __launch_bounds__(128, 3)
k_zgemm(float* __restrict__ dout, int N) {
    extern __shared__ float4 sB4[];   // [JD][NGP] = 156*27*16 = 67392 B
    int tid = threadIdx.x;
    int n0 = blockIdx.x * 128;

    for (int idx = tid; idx < JD * NG; idx += 128) {
        int j = idx / NG, g = idx - j * NG;
        const float* m = g_M + j * CD + 3 * g;
        sB4[j * NGP + g] = make_float4(m[0], m[1], m[2], 0.f);
    }
    __syncthreads();

    int half = tid >> 6;          // 0 or 1
    int r    = tid & 63;          // node-pair index
    int na = n0 + 2 * r;
    int nb = na + 1;
    bool va = (na < N), vb = (nb < N);

    const float4* sB = sB4 + half * GH;   // this half's column base

    float accA[GH][3], accB[GH][3];
#pragma unroll
    for (int g = 0; g < GH; g++) {
        accA[g][0] = accA[g][1] = accA[g][2] = 0.f;
        accB[g][0] = accB[g][1] = accB[g][2] = 0.f;
    }

    const float4* HA = reinterpret_cast<const float4*>(g_H + (size_t)na * HROW);
    const float4* HB = reinterpret_cast<const float4*>(g_H + (size_t)nb * HROW);
    float dA = 0.f, dB = 0.f;
    const float4 z4 = make_float4(0.f, 0.f, 0.f, 0.f);

    for (int k = 0; k < NKER; k++) {
        float4 ha0 = va ? __ldg(HA + 2 * k)     : z4;
        float4 ha1 = va ? __ldg(HA + 2 * k + 1) : z4;
        float4 hb0 = vb ? __ldg(HB + 2 * k)     : z4;
        float4 hb1 = vb ? __ldg(HB + 2 * k + 1) : z4;
        dA += ha1.z; dB += hb1.z;
        float avA[6] = {ha0.x, ha0.y, ha0.z, ha0.w, ha1.x, ha1.y};
        float avB[6] = {hb0.x, hb0.y, hb0.z, hb0.w, hb1.x, hb1.y};
#pragma unroll
        for (int i = 0; i < 6; i++) {
            float aA = avA[i], aB = avB[i];
            const float4* mrow = sB + (k * 6 + i) * NGP;
#pragma unroll
            for (int g = 0; g < GH; g++) {
                float4 b = mrow[g];
                accA[g][0] = fmaf(aA, b.x, accA[g][0]);
                accA[g][1] = fmaf(aA, b.y, accA[g][1]);
                accA[g][2] = fmaf(aA, b.z, accA[g][2]);
                accB[g][0] = fmaf(aB, b.x, accB[g][0]);
                accB[g][1] = fmaf(aB, b.y, accB[g][1]);
                accB[g][2] = fmaf(aB, b.z, accB[g][2]);
            }
        }
    }

    float invA = 1.0f / fmaxf(dA, 1.0f);
    float invB = 1.0f / fmaxf(dB, 1.0f);
    if (half == 0) {
        if (va) g_inv[na] = invA;
        if (vb) g_inv[nb] = invB;
    }
#pragma unroll
    for (int g = 0; g < GH; g++) {
        accA[g][0] *= invA; accA[g][1] *= invA; accA[g][2] *= invA;
        accB[g][0] *= invB; accB[g][1] *= invB; accB[g][2] *= invB;
    }

    // x part (rows 150..155 of M), unscaled — both halves, own columns
    float4 xaA = va ? __ldg(g_X8 + 2 * na)     : z4;
    float4 xbA = va ? __ldg(g_X8 + 2 * na + 1) : z4;
    float4 xaB = vb ? __ldg(g_X8 + 2 * nb)     : z4;
    float4 xbB = vb ? __ldg(g_X8 + 2 * nb + 1) : z4;
    float xvA[6] = {xaA.x, xaA.y, xaA.z, xaA.w, xbA.x, xbA.y};
    float xvB[6] = {xaB.x, xaB.y, xaB.z, xaB.w, xbB.x, xbB.y};
#pragma unroll
    for (int i = 0; i < 6; i++) {
        float aA = xvA[i], aB = xvB[i];
        const float4* mrow = sB + (HW + i) * NGP;
#pragma unroll
        for (int g = 0; g < GH; g++) {
            float4 b = mrow[g];
            accA[g][0] = fmaf(aA, b.x, accA[g][0]);
            accA[g][1] = fmaf(aA, b.y, accA[g][1]);
            accA[g][2] = fmaf(aA, b.z, accA[g][2]);
            accB[g][0] = fmaf(aB, b.x, accB[g][0]);
            accB[g][1] = fmaf(aB, b.y, accB[g][1]);
            accB[g][2] = fmaf(aB, b.z, accB[g][2]);
        }
    }

    // stores: half0 -> kk 0..12 ; half1 -> kk 13..24 + root cols
    if (half == 0) {
        if (va) {
            float4* Zn = g_Z4 + (size_t)na * NKER;
#pragma unroll
            for (int g = 0; g < GH; g++)
                Zn[g] = make_float4(accA[g][0], accA[g][1], accA[g][2], 0.f);
        }
        if (vb) {
            float4* Zn = g_Z4 + (size_t)nb * NKER;
#pragma unroll
            for (int g = 0; g < GH; g++)
                Zn[g] = make_float4(accB[g][0], accB[g][1], accB[g][2], 0.f);
        }
    } else {
        if (va) {
            float4* Zn = g_Z4 + (size_t)na * NKER;
#pragma unroll
            for (int g = 0; g < GH - 1; g++)
                Zn[13 + g] = make_float4(accA[g][0], accA[g][1], accA[g][2], 0.f);
            dout[na * 3 + 0] = accA[GH - 1][0];
            dout[na * 3 + 1] = accA[GH - 1][1];
            dout[na * 3 + 2] = accA[GH - 1][2];
        }
        if (vb) {
            float4* Zn = g_Z4 + (size_t)nb * NKER;
#pragma unroll
            for (int g = 0; g < GH - 1; g++)
                Zn[13 + g] = make_float4(accB[g][0], accB[g][1], accB[g][2], 0.f);
            dout[nb * 3 + 0] = accB[GH - 1][0];
            dout[nb * 3 + 1] = accB[GH - 1][1];
            dout[nb * 3 + 2] = accB[GH - 1][2];
        }
    }
}

// ---------------------------------------------------------------------------
// Edge pass 2: A4[dst] += sum_s basis1_s * Z[src, idx_s, :]  (one float4 atomic)
__global__ void k_edge2(const int* __restrict__ ei, const float* __restrict__ ps,
                        int E) {
    int e = blockIdx.x * blockDim.x + threadIdx.x;
    if (e >= E) return;
    int dst = ei[e];
    int src = ei[E + e];
    float2 p = reinterpret_cast<const float2*>(ps)[e];
    float b[4]; int id[4];
    spline4(p.x, p.y, b, id);
    const float4* Z = g_Z4 + (size_t)src * NKER;
    float a0 = 0.f, a1 = 0.f, a2 = 0.f;
#pragma unroll
    for (int s = 0; s < 4; s++) {
        float4 z = __ldg(Z + id[s]);
        a0 = fmaf(b[s], z.x, a0);
        a1 = fmaf(b[s], z.y, a1);
        a2 = fmaf(b[s], z.z, a2);
    }
    atomicAdd(g_A4 + dst, make_float4(a0, a1, a2, 0.f));
}

// ---------------------------------------------------------------------------
// Final: out[n] = root_term (already in dout) + inv[n] * A4[n]
__global__ void k_final(float* __restrict__ dout, int N) {
    int n = blockIdx.x * blockDim.x + threadIdx.x;
    if (n >= N) return;
    float4 a = g_A4[n];
    float inv = g_inv[n];
    dout[n * 3 + 0] += a.x * inv;
    dout[n * 3 + 1] += a.y * inv;
    dout[n * 3 + 2] += a.z * inv;
}

// ---------------------------------------------------------------------------
extern "C" void kernel_launch(void* const* d_in, const int* in_sizes, int n_in,
                              void* d_out, int out_size) {
    const float* x   = (const float*)d_in[0];
    const int*   ei  = (const int*)d_in[1];
    const float* ps  = (const float*)d_in[2];
    const float* ps1 = (const float*)d_in[3];
    const float* w   = (const float*)d_in[4];
    const float* rw  = (const float*)d_in[5];
    const float* w1  = (const float*)d_in[6];
    const float* rw1 = (const float*)d_in[7];
    float* dout = (float*)d_out;

    int N = in_sizes[0] / 6;
    int E = in_sizes[2] / 2;
    if (N > NMAX) N = NMAX;
    if (E > EMAX) E = EMAX;

    k_zero<<<2048, 256>>>(x, N);
    k_edge1<<<(E + 255) / 256, 256>>>(ei, ps, E);
    k_buildM<<<JD, 320>>>(w, rw, w1, rw1);

    size_t smemC = (size_t)(JD * NGP) * sizeof(float4);   // 67392 B
    cudaFuncSetAttribute(k_zgemm, cudaFuncAttributeMaxDynamicSharedMemorySize, (int)smemC);
    k_zgemm<<<(N + 127) / 128, 128, smemC>>>(dout, N);

    k_edge2<<<(E + 255) / 256, 256>>>(ei, ps1, E);
    k_final<<<(N + 255) / 256, 256>>>(dout, N);
}